// round 1
// baseline (speedup 1.0000x reference)
#include <cuda_runtime.h>
#include <math.h>

// ---------------- problem constants ----------------
#define SEQ   256
#define BATCH 2
#define HIDD  512
#define NHEAD 8
#define HDIM  64
#define NROW  512              // BATCH*SEQ
#define CHB   2048             // chunks per batch = SEQ*NHEAD
#define EPSN  1e-15f
#define MAXNORM 0.996f         // (1-4e-3)/sqrt(c), c=1

// ---------------- device scratch (static, allowed) ----------------
__device__ float g_mx[3 * NROW * HIDD];        // GEMM outputs (3 MB)
__device__ float g_q[NROW * HIDD];             // ql chunks, flat [b][s'][512]
__device__ float g_k[NROW * HIDD];
__device__ float g_v[NROW * HIDD];
__device__ float g_q2[BATCH * CHB];            // |ql chunk|^2
__device__ float g_k2[BATCH * CHB];
__device__ float g_gamma[BATCH * CHB];         // 2/max(1-|vl|^2,eps)
__device__ float g_u[NROW * HIDD];             // tangent ctx, layout [b][q][h*64+d]
__device__ float g_probs[BATCH * NHEAD * SEQ * SEQ]; // fallback if out lacks probs

__device__ __forceinline__ float atanh_c(float x) {
    x = fminf(fmaxf(x, -0.9999999f), 0.9999999f);
    return atanhf(x);
}
__device__ __forceinline__ float dot4(float4 a, float4 b) {
    return a.x * b.x + a.y * b.y + a.z * b.z + a.w * b.w;
}
__device__ __forceinline__ float blkred(float v, float* sm) {
    #pragma unroll
    for (int o = 16; o; o >>= 1) v += __shfl_xor_sync(0xffffffffu, v, o);
    if ((threadIdx.x & 31) == 0) sm[threadIdx.x >> 5] = v;
    __syncthreads();
    v = sm[0] + sm[1] + sm[2] + sm[3];
    __syncthreads();
    return v;
}

// ================= K1: mx = x @ W^T for q,k,v  =================
// A row r = b*256+s'  maps to query[(s'*B + b)*512 + k]
__global__ __launch_bounds__(256) void gemm_kernel(
    const float* __restrict__ query,
    const float* __restrict__ Wq,
    const float* __restrict__ Wk,
    const float* __restrict__ Wv)
{
    __shared__ float As[16][68];
    __shared__ float Bs[16][68];
    int mat = blockIdx.z;
    const float* W = (mat == 0) ? Wq : (mat == 1 ? Wk : Wv);
    float* out = g_mx + mat * NROW * HIDD;
    int t = threadIdx.x;
    int tx = t & 15, ty = t >> 4;
    int row0 = blockIdx.y << 6, col0 = blockIdx.x << 6;

    float acc[4][4];
    #pragma unroll
    for (int i = 0; i < 4; i++)
        #pragma unroll
        for (int j = 0; j < 4; j++) acc[i][j] = 0.f;

    for (int k0 = 0; k0 < HIDD; k0 += 16) {
        #pragma unroll
        for (int li = t; li < 1024; li += 256) {
            int i = li >> 4, kk = li & 15;
            int r = row0 + i;
            As[kk][i] = query[((((r & 255) << 1) + (r >> 8)) << 9) + k0 + kk];
            Bs[kk][i] = W[((col0 + i) << 9) + k0 + kk];
        }
        __syncthreads();
        #pragma unroll
        for (int kk = 0; kk < 16; kk++) {
            float4 a  = *(const float4*)&As[kk][ty << 2];
            float4 bb = *(const float4*)&Bs[kk][tx << 2];
            float av[4] = {a.x, a.y, a.z, a.w};
            float bv[4] = {bb.x, bb.y, bb.z, bb.w};
            #pragma unroll
            for (int i = 0; i < 4; i++)
                #pragma unroll
                for (int j = 0; j < 4; j++)
                    acc[i][j] = fmaf(av[i], bv[j], acc[i][j]);
        }
        __syncthreads();
    }
    #pragma unroll
    for (int i = 0; i < 4; i++) {
        float4 o = {acc[i][0], acc[i][1], acc[i][2], acc[i][3]};
        *(float4*)(out + ((row0 + (ty << 2) + i) << 9) + col0 + (tx << 2)) = o;
    }
}

// ===== K2: per-row mobius_matvec norm map + mobius_add bias + projx +
//           logmap0(512) + per-64-chunk expmap0 + chunk stats =====
__global__ __launch_bounds__(128) void epilogue_kernel(
    const float* __restrict__ query,
    const float* __restrict__ bq,
    const float* __restrict__ bk,
    const float* __restrict__ bv)
{
    __shared__ float red[4];
    int bid = blockIdx.x;
    int mat = bid >> 9;          // 0..2
    int r = bid & 511;           // b*256 + s'
    int b = r >> 8, sp = r & 255;
    const float* bias_p = (mat == 0) ? bq : (mat == 1 ? bk : bv);
    float* outp = (mat == 0) ? g_q : (mat == 1 ? g_k : g_v);
    int t = threadIdx.x;

    float4 x  = *(const float4*)(query + ((sp * BATCH + b) << 9) + 4 * t);
    float4 m  = *(const float4*)(g_mx + mat * NROW * HIDD + (r << 9) + 4 * t);
    float4 bi = *(const float4*)(bias_p + 4 * t);

    float sxx = blkred(dot4(x, x), red);
    float smm = blkred(dot4(m, m), red);
    float xn = fmaxf(sqrtf(sxx), EPSN);
    float mn = fmaxf(sqrtf(smm), EPSN);
    float sc1 = tanhf(mn / xn * atanh_c(xn)) / mn;
    float4 res = {sc1 * m.x, sc1 * m.y, sc1 * m.z, sc1 * m.w};

    float x2 = blkred(dot4(res, res), red);
    float xy = blkred(dot4(res, bi), red);
    float y2 = blkred(dot4(bi, bi), red);
    float ac = 1.f + 2.f * xy + y2;
    float bc = 1.f - x2;
    float den = fmaxf(1.f + 2.f * xy + x2 * y2, EPSN);
    float idn = 1.f / den;
    float4 z = {(ac * res.x + bc * bi.x) * idn, (ac * res.y + bc * bi.y) * idn,
                (ac * res.z + bc * bi.z) * idn, (ac * res.w + bc * bi.w) * idn};

    float z2 = blkred(dot4(z, z), red);
    float nz = fmaxf(sqrtf(z2), EPSN);
    float ps = (nz > MAXNORM) ? (MAXNORM / nz) : 1.f;
    float nzc = nz * ps;                       // = min(nz, MAXNORM)
    float us = atanh_c(nzc) / fmaxf(nzc, EPSN) * ps;   // u = us * z
    float4 u = {us * z.x, us * z.y, us * z.z, us * z.w};

    // per-64-chunk expmap0: thread's 4 elems (c=4t..4t+3) are all in chunk t/16
    float cs = dot4(u, u);
    #pragma unroll
    for (int o = 8; o; o >>= 1) cs += __shfl_xor_sync(0xffffffffu, cs, o, 16);
    float cn = fmaxf(sqrtf(cs), EPSN);
    float csc = tanhf(cn) / cn;
    float4 o4 = {csc * u.x, csc * u.y, csc * u.z, csc * u.w};
    *(float4*)(outp + (r << 9) + 4 * t) = o4;

    if ((t & 15) == 0) {
        float o2 = csc * csc * cs;             // |chunk|^2 of output
        int cid = b * CHB + sp * 8 + (t >> 4); // flat chunk id == h*256+s
        if (mat == 0)      g_q2[cid] = o2;
        else if (mat == 1) g_k2[cid] = o2;
        else               g_gamma[cid] = 2.f / fmaxf(1.f - o2, EPSN);
    }
}

// ===== K3: scores -> probs.  64x64 (q,n) tile per block. =====
// probs = (1 - clip(t1)) / 2   [sigmoid(-2 artanh(t1)) identity]
__global__ __launch_bounds__(256, 2) void score_kernel(float* __restrict__ probs_ext)
{
    __shared__ float qsm[64][65];
    __shared__ float ksm[64][65];
    __shared__ float q2s[64];
    __shared__ float k2s[64];
    float* probs = probs_ext ? probs_ext : g_probs;

    int bh = blockIdx.z;
    int b = bh >> 3, h = bh & 7;
    int q0 = blockIdx.y << 6, n0 = blockIdx.x << 6;
    const float* Qp = g_q + b * 131072 + ((h << 8) + q0) * 64;
    const float* Kp = g_k + b * 131072 + ((h << 8) + n0) * 64;
    int t = threadIdx.x;

    for (int li = t; li < 4096; li += 256) {
        qsm[li >> 6][li & 63] = Qp[li];
        ksm[li >> 6][li & 63] = Kp[li];
    }
    if (t < 64) {
        q2s[t] = g_q2[b * CHB + (h << 8) + q0 + t];
        k2s[t] = g_k2[b * CHB + (h << 8) + n0 + t];
    }
    __syncthreads();

    int qi = t >> 2, nl = t & 3;
    float qr[64];
    #pragma unroll
    for (int d = 0; d < 64; d++) qr[d] = qsm[qi][d];
    float q2 = q2s[qi];
    float Bc = 1.f - q2;
    float* orow = probs + ((bh << 8) + q0 + qi) * 256 + n0;

    #pragma unroll 1
    for (int jj = 0; jj < 16; jj++) {
        int n = (jj << 2) | nl;
        float dot = 0.f;
        #pragma unroll
        for (int d = 0; d < 64; d++) dot = fmaf(qr[d], ksm[n][d], dot);
        float k2 = k2s[n];
        float A = 1.f - 2.f * dot + k2;        // coeff of (-q)
        float den = fmaxf(fmaf(q2, k2, 1.f - 2.f * dot), EPSN);
        float invd = __fdividef(1.f, den);
        float acc = 0.f;
        #pragma unroll
        for (int d = 0; d < 64; d++) {
            float w = fmaf(Bc, ksm[n][d], -A * qr[d]);
            float diff = w * invd;
            float d2 = diff * diff;
            acc += fminf(__fdividef(1.f, d2), 1e30f);   // min(1/d2,1e30)==max(d2,1e-30)^-1
        }
        float t1 = rsqrtf(acc);
        t1 = fminf(t1, 0.9999999f);
        orow[n] = 0.5f - 0.5f * t1;
    }
}

// ===== K4: weighted gyro-midpoint + fused scalar_mul(0.5)+logmap0 =====
__global__ __launch_bounds__(256) void ctx_kernel(const float* __restrict__ probs_ext)
{
    __shared__ float psm[32][65];
    __shared__ float vsm[64][68];
    __shared__ float gm1[64];
    const float* probs = probs_ext ? probs_ext : g_probs;

    int bh = blockIdx.y;
    int b = bh >> 3, h = bh & 7;
    int q0 = blockIdx.x << 5;
    int t = threadIdx.x;
    int qi = t >> 3, dg = t & 7;

    const float* Vb  = g_v + b * 131072 + (h << 14);
    const float* gmb = g_gamma + b * CHB + (h << 8);
    const float* pb  = probs + ((bh << 8) + q0) * 256;

    float nom[8];
    #pragma unroll
    for (int j = 0; j < 8; j++) nom[j] = 0.f;
    float dacc = 0.f;

    for (int nt = 0; nt < 4; nt++) {
        __syncthreads();
        for (int li = t; li < 2048; li += 256)
            psm[li >> 6][li & 63] = pb[(li >> 6) * 256 + (nt << 6) + (li & 63)];
        for (int li = t; li < 4096; li += 256) {
            int n = li >> 6, d = li & 63;
            vsm[n][d] = Vb[(((nt << 6) + n) << 6) + d] * gmb[(nt << 6) + n];
        }
        if (t < 64) gm1[t] = gmb[(nt << 6) + t] - 1.f;
        __syncthreads();
        #pragma unroll 4
        for (int n = 0; n < 64; n++) {
            float p = psm[qi][n];
            dacc = fmaf(p, gm1[n], dacc);
            const float* vr = &vsm[n][dg << 3];
            #pragma unroll
            for (int j = 0; j < 8; j++) nom[j] = fmaf(p, vr[j], nom[j]);
        }
    }

    // denom sign/floor, ctx0 = nom/denom, then u = 0.5*atanh(|ctx0|)/|ctx0| * ctx0
    float dn = fmaxf(fabsf(dacc), 1e-10f);
    if (dacc < 0.f) dn = -dn;
    float idn = 1.f / dn;
    float c0[8]; float ss = 0.f;
    #pragma unroll
    for (int j = 0; j < 8; j++) { c0[j] = nom[j] * idn; ss += c0[j] * c0[j]; }
    #pragma unroll
    for (int o = 4; o; o >>= 1) ss += __shfl_xor_sync(0xffffffffu, ss, o, 8);
    float nn = fmaxf(sqrtf(ss), EPSN);
    float usc = 0.5f * atanh_c(nn) / nn;
    float* up = g_u + ((b << 8) + q0 + qi) * 512 + (h << 6) + (dg << 3);
    #pragma unroll
    for (int j = 0; j < 8; j++) up[j] = usc * c0[j];
}

// ===== K5: final expmap0 over concatenated 512 + output transpose =====
__global__ __launch_bounds__(128) void final_kernel(float* __restrict__ out)
{
    __shared__ float red[4];
    int r = blockIdx.x;            // b*256 + q
    int b = r >> 8, q = r & 255;
    int t = threadIdx.x;
    float4 u = *(const float4*)(g_u + (r << 9) + 4 * t);
    float s = blkred(dot4(u, u), red);
    float nn = fmaxf(sqrtf(s), EPSN);
    float sc = tanhf(nn) / nn;
    float4 o = {sc * u.x, sc * u.y, sc * u.z, sc * u.w};
    *(float4*)(out + ((q * BATCH + b) << 9) + 4 * t) = o;
}

// ---------------- launch ----------------
extern "C" void kernel_launch(void* const* d_in, const int* in_sizes, int n_in,
                              void* d_out, int out_size)
{
    const float* query = (const float*)d_in[0];
    const float* Wq = (const float*)d_in[1];
    const float* bq = (const float*)d_in[2];
    const float* Wk = (const float*)d_in[3];
    const float* bk = (const float*)d_in[4];
    const float* Wv = (const float*)d_in[5];
    const float* bv = (const float*)d_in[6];
    float* out = (float*)d_out;

    // output layout: ctx [S,B,HID] (262144) then probs [B,H,S,S] (1048576)
    float* probs = (out_size >= 262144 + 1048576) ? (out + 262144) : (float*)0;

    gemm_kernel<<<dim3(8, 8, 3), 256>>>(query, Wq, Wk, Wv);
    epilogue_kernel<<<1536, 128>>>(query, bq, bk, bv);
    score_kernel<<<dim3(4, 4, 16), 256>>>(probs);
    ctx_kernel<<<dim3(8, 16), 256>>>(probs);
    final_kernel<<<512, 128>>>(out);
}

// round 2
// speedup vs baseline: 1.1594x; 1.1594x over previous
#include <cuda_runtime.h>
#include <math.h>

// ---------------- problem constants ----------------
#define SEQ   256
#define BATCH 2
#define HIDD  512
#define NHEAD 8
#define HDIM  64
#define NROW  512              // BATCH*SEQ
#define CHB   2048             // chunks per batch = SEQ*NHEAD
#define EPSN  1e-15f
#define MAXNORM 0.996f         // (1-4e-3)/sqrt(c), c=1

// ---------------- device scratch (static, allowed) ----------------
__device__ float g_mx[3 * NROW * HIDD];        // GEMM outputs (3 MB)
__device__ float g_q[NROW * HIDD];             // ql chunks, flat [b][s'][512]
__device__ float g_k[NROW * HIDD];
__device__ float g_v[NROW * HIDD];
__device__ float g_q2[BATCH * CHB];            // |ql chunk|^2
__device__ float g_k2[BATCH * CHB];
__device__ float g_gamma[BATCH * CHB];         // 2/max(1-|vl|^2,eps)
__device__ float g_u[NROW * HIDD];             // tangent ctx, layout [b][q][h*64+d]
__device__ float g_probs[BATCH * NHEAD * SEQ * SEQ]; // fallback if out lacks probs

__device__ __forceinline__ float atanh_c(float x) {
    x = fminf(fmaxf(x, -0.9999999f), 0.9999999f);
    return atanhf(x);
}
__device__ __forceinline__ float dot4(float4 a, float4 b) {
    return a.x * b.x + a.y * b.y + a.z * b.z + a.w * b.w;
}
__device__ __forceinline__ float blkred(float v, float* sm) {
    #pragma unroll
    for (int o = 16; o; o >>= 1) v += __shfl_xor_sync(0xffffffffu, v, o);
    if ((threadIdx.x & 31) == 0) sm[threadIdx.x >> 5] = v;
    __syncthreads();
    v = sm[0] + sm[1] + sm[2] + sm[3];
    __syncthreads();
    return v;
}

// ================= K1: mx = x @ W^T for q,k,v  =================
// A row r = b*256+s'  maps to query[(s'*B + b)*512 + k]
__global__ __launch_bounds__(256) void gemm_kernel(
    const float* __restrict__ query,
    const float* __restrict__ Wq,
    const float* __restrict__ Wk,
    const float* __restrict__ Wv)
{
    __shared__ float As[16][68];
    __shared__ float Bs[16][68];
    int mat = blockIdx.z;
    const float* W = (mat == 0) ? Wq : (mat == 1 ? Wk : Wv);
    float* out = g_mx + mat * NROW * HIDD;
    int t = threadIdx.x;
    int tx = t & 15, ty = t >> 4;
    int row0 = blockIdx.y << 6, col0 = blockIdx.x << 6;

    float acc[4][4];
    #pragma unroll
    for (int i = 0; i < 4; i++)
        #pragma unroll
        for (int j = 0; j < 4; j++) acc[i][j] = 0.f;

    for (int k0 = 0; k0 < HIDD; k0 += 16) {
        #pragma unroll
        for (int li = t; li < 1024; li += 256) {
            int i = li >> 4, kk = li & 15;
            int r = row0 + i;
            As[kk][i] = query[((((r & 255) << 1) + (r >> 8)) << 9) + k0 + kk];
            Bs[kk][i] = W[((col0 + i) << 9) + k0 + kk];
        }
        __syncthreads();
        #pragma unroll
        for (int kk = 0; kk < 16; kk++) {
            float4 a  = *(const float4*)&As[kk][ty << 2];
            float4 bb = *(const float4*)&Bs[kk][tx << 2];
            float av[4] = {a.x, a.y, a.z, a.w};
            float bv[4] = {bb.x, bb.y, bb.z, bb.w};
            #pragma unroll
            for (int i = 0; i < 4; i++)
                #pragma unroll
                for (int j = 0; j < 4; j++)
                    acc[i][j] = fmaf(av[i], bv[j], acc[i][j]);
        }
        __syncthreads();
    }
    #pragma unroll
    for (int i = 0; i < 4; i++) {
        float4 o = {acc[i][0], acc[i][1], acc[i][2], acc[i][3]};
        *(float4*)(out + ((row0 + (ty << 2) + i) << 9) + col0 + (tx << 2)) = o;
    }
}

// ===== K2: per-row mobius_matvec norm map + mobius_add bias + projx +
//           logmap0(512) + per-64-chunk expmap0 + chunk stats =====
__global__ __launch_bounds__(128) void epilogue_kernel(
    const float* __restrict__ query,
    const float* __restrict__ bq,
    const float* __restrict__ bk,
    const float* __restrict__ bv)
{
    __shared__ float red[4];
    int bid = blockIdx.x;
    int mat = bid >> 9;          // 0..2
    int r = bid & 511;           // b*256 + s'
    int b = r >> 8, sp = r & 255;
    const float* bias_p = (mat == 0) ? bq : (mat == 1 ? bk : bv);
    float* outp = (mat == 0) ? g_q : (mat == 1 ? g_k : g_v);
    int t = threadIdx.x;

    float4 x  = *(const float4*)(query + ((sp * BATCH + b) << 9) + 4 * t);
    float4 m  = *(const float4*)(g_mx + mat * NROW * HIDD + (r << 9) + 4 * t);
    float4 bi = *(const float4*)(bias_p + 4 * t);

    float sxx = blkred(dot4(x, x), red);
    float smm = blkred(dot4(m, m), red);
    float xn = fmaxf(sqrtf(sxx), EPSN);
    float mn = fmaxf(sqrtf(smm), EPSN);
    float sc1 = tanhf(mn / xn * atanh_c(xn)) / mn;
    float4 res = {sc1 * m.x, sc1 * m.y, sc1 * m.z, sc1 * m.w};

    float x2 = blkred(dot4(res, res), red);
    float xy = blkred(dot4(res, bi), red);
    float y2 = blkred(dot4(bi, bi), red);
    float ac = 1.f + 2.f * xy + y2;
    float bc = 1.f - x2;
    float den = fmaxf(1.f + 2.f * xy + x2 * y2, EPSN);
    float idn = 1.f / den;
    float4 z = {(ac * res.x + bc * bi.x) * idn, (ac * res.y + bc * bi.y) * idn,
                (ac * res.z + bc * bi.z) * idn, (ac * res.w + bc * bi.w) * idn};

    float z2 = blkred(dot4(z, z), red);
    float nz = fmaxf(sqrtf(z2), EPSN);
    float ps = (nz > MAXNORM) ? (MAXNORM / nz) : 1.f;
    float nzc = nz * ps;                       // = min(nz, MAXNORM)
    float us = atanh_c(nzc) / fmaxf(nzc, EPSN) * ps;   // u = us * z
    float4 u = {us * z.x, us * z.y, us * z.z, us * z.w};

    // per-64-chunk expmap0: thread's 4 elems (c=4t..4t+3) are all in chunk t/16
    float cs = dot4(u, u);
    #pragma unroll
    for (int o = 8; o; o >>= 1) cs += __shfl_xor_sync(0xffffffffu, cs, o, 16);
    float cn = fmaxf(sqrtf(cs), EPSN);
    float csc = tanhf(cn) / cn;
    float4 o4 = {csc * u.x, csc * u.y, csc * u.z, csc * u.w};
    *(float4*)(outp + (r << 9) + 4 * t) = o4;

    if ((t & 15) == 0) {
        float o2 = csc * csc * cs;             // |chunk|^2 of output
        int cid = b * CHB + sp * 8 + (t >> 4); // flat chunk id == h*256+s
        if (mat == 0)      g_q2[cid] = o2;
        else if (mat == 1) g_k2[cid] = o2;
        else               g_gamma[cid] = 2.f / fmaxf(1.f - o2, EPSN);
    }
}

// ===== K3: scores -> probs.  64x64 (q,n) tile per block. =====
// probs = (1 - clip(t1)) / 2   [sigmoid(-2 artanh(t1)) identity]
__global__ __launch_bounds__(256, 2) void score_kernel(float* __restrict__ probs_ext)
{
    __shared__ float qsm[64][65];
    __shared__ float ksm[64][65];
    __shared__ float q2s[64];
    __shared__ float k2s[64];
    float* probs = probs_ext ? probs_ext : g_probs;

    int bh = blockIdx.z;
    int b = bh >> 3, h = bh & 7;
    int q0 = blockIdx.y << 6, n0 = blockIdx.x << 6;
    const float* Qp = g_q + b * 131072 + ((h << 8) + q0) * 64;
    const float* Kp = g_k + b * 131072 + ((h << 8) + n0) * 64;
    int t = threadIdx.x;

    for (int li = t; li < 4096; li += 256) {
        qsm[li >> 6][li & 63] = Qp[li];
        ksm[li >> 6][li & 63] = Kp[li];
    }
    if (t < 64) {
        q2s[t] = g_q2[b * CHB + (h << 8) + q0 + t];
        k2s[t] = g_k2[b * CHB + (h << 8) + n0 + t];
    }
    __syncthreads();

    int qi = t >> 2, nl = t & 3;
    float qr[64];
    #pragma unroll
    for (int d = 0; d < 64; d++) qr[d] = qsm[qi][d];
    float q2 = q2s[qi];
    float Bc = 1.f - q2;
    float* orow = probs + ((bh << 8) + q0 + qi) * 256 + n0;

    #pragma unroll 1
    for (int jj = 0; jj < 16; jj++) {
        int n = (jj << 2) | nl;
        float dot = 0.f;
        #pragma unroll
        for (int d = 0; d < 64; d++) dot = fmaf(qr[d], ksm[n][d], dot);
        float k2 = k2s[n];
        float A = 1.f - 2.f * dot + k2;        // coeff of (-q)
        float den = fmaxf(fmaf(q2, k2, 1.f - 2.f * dot), EPSN);
        float invd = __fdividef(1.f, den);
        float acc = 0.f;
        #pragma unroll
        for (int d = 0; d < 64; d++) {
            float w = fmaf(Bc, ksm[n][d], -A * qr[d]);
            float diff = w * invd;
            float d2 = diff * diff;
            acc += fminf(__fdividef(1.f, d2), 1e30f);   // min(1/d2,1e30)==max(d2,1e-30)^-1
        }
        float t1 = rsqrtf(acc);
        t1 = fminf(t1, 0.9999999f);
        orow[n] = 0.5f - 0.5f * t1;
    }
}

// ===== K4: weighted gyro-midpoint + fused scalar_mul(0.5)+logmap0 =====
// Register-tiled batched GEMM: nom[16q x 64d] += probs[16q x 256n] @ (gamma*v)[256n x 64d]
// grid (16 q-tiles, 16 bh), 256 threads, thread = (qi, dh): 1 q-row x float4 of d.
__global__ __launch_bounds__(256) void ctx_kernel(const float* __restrict__ probs_ext)
{
    __shared__ float  psm[16][64];     // probs tile (broadcast reads)
    __shared__ float4 vsm[64][17];     // gamma*v tile, padded: conflict-free LDS.128
    __shared__ float  gm1[64];
    const float* probs = probs_ext ? probs_ext : g_probs;

    int bh = blockIdx.y;               // b*8 + h
    int b = bh >> 3, h = bh & 7;
    int q0 = blockIdx.x << 4;          // 16 q rows per block
    int t = threadIdx.x;
    int qi = t >> 4, dh = t & 15;

    const float* Vb  = g_v + b * 131072 + (h << 14);
    const float* gmb = g_gamma + b * CHB + (h << 8);
    const float* pb  = probs + ((bh << 8) + q0) * 256;

    float4 nom = {0.f, 0.f, 0.f, 0.f};
    float dacc = 0.f;

    #pragma unroll 1
    for (int nt = 0; nt < 4; nt++) {
        __syncthreads();
        // probs tile: 16 rows x 64 n
        for (int li = t; li < 1024; li += 256)
            psm[li >> 6][li & 63] = pb[(li >> 6) * 256 + (nt << 6) + (li & 63)];
        // gamma*v tile: 64 n x 64 d as float4
        for (int li = t; li < 1024; li += 256) {
            int n = li >> 4, d4 = li & 15;
            float g = gmb[(nt << 6) + n];
            float4 v = *(const float4*)(Vb + (((nt << 6) + n) << 6) + (d4 << 2));
            vsm[n][d4] = make_float4(v.x * g, v.y * g, v.z * g, v.w * g);
        }
        if (t < 64) gm1[t] = gmb[(nt << 6) + t] - 1.f;
        __syncthreads();
        #pragma unroll 4
        for (int n = 0; n < 64; n++) {
            float p = psm[qi][n];
            float4 v = vsm[n][dh];
            nom.x = fmaf(p, v.x, nom.x);
            nom.y = fmaf(p, v.y, nom.y);
            nom.z = fmaf(p, v.z, nom.z);
            nom.w = fmaf(p, v.w, nom.w);
            dacc = fmaf(p, gm1[n], dacc);
        }
    }

    // denom sign/floor, ctx0 = nom/denom, then u = 0.5*atanh(|ctx0|)/|ctx0| * ctx0
    float dn = fmaxf(fabsf(dacc), 1e-10f);
    if (dacc < 0.f) dn = -dn;
    float idn = 1.f / dn;
    float4 c0 = {nom.x * idn, nom.y * idn, nom.z * idn, nom.w * idn};
    float ss = dot4(c0, c0);
    // reduce over the 16-thread d-group (lanes [g*16, g*16+15] share qi)
    #pragma unroll
    for (int o = 8; o; o >>= 1) ss += __shfl_xor_sync(0xffffffffu, ss, o, 16);
    float nn = fmaxf(sqrtf(ss), EPSN);
    float usc = 0.5f * atanh_c(nn) / nn;
    float4 u = {usc * c0.x, usc * c0.y, usc * c0.z, usc * c0.w};
    *(float4*)(g_u + ((b << 8) + q0 + qi) * 512 + (h << 6) + (dh << 2)) = u;
}

// ===== K5: final expmap0 over concatenated 512 + output transpose =====
__global__ __launch_bounds__(128) void final_kernel(float* __restrict__ out)
{
    __shared__ float red[4];
    int r = blockIdx.x;            // b*256 + q
    int b = r >> 8, q = r & 255;
    int t = threadIdx.x;
    float4 u = *(const float4*)(g_u + (r << 9) + 4 * t);
    float s = blkred(dot4(u, u), red);
    float nn = fmaxf(sqrtf(s), EPSN);
    float sc = tanhf(nn) / nn;
    float4 o = {sc * u.x, sc * u.y, sc * u.z, sc * u.w};
    *(float4*)(out + ((q * BATCH + b) << 9) + 4 * t) = o;
}

// ---------------- launch ----------------
extern "C" void kernel_launch(void* const* d_in, const int* in_sizes, int n_in,
                              void* d_out, int out_size)
{
    const float* query = (const float*)d_in[0];
    const float* Wq = (const float*)d_in[1];
    const float* bq = (const float*)d_in[2];
    const float* Wk = (const float*)d_in[3];
    const float* bk = (const float*)d_in[4];
    const float* Wv = (const float*)d_in[5];
    const float* bv = (const float*)d_in[6];
    float* out = (float*)d_out;

    // output layout: ctx [S,B,HID] (262144) then probs [B,H,S,S] (1048576)
    float* probs = (out_size >= 262144 + 1048576) ? (out + 262144) : (float*)0;

    gemm_kernel<<<dim3(8, 8, 3), 256>>>(query, Wq, Wk, Wv);
    epilogue_kernel<<<1536, 128>>>(query, bq, bk, bv);
    score_kernel<<<dim3(4, 4, 16), 256>>>(probs);
    ctx_kernel<<<dim3(16, 16), 256>>>(probs);
    final_kernel<<<512, 128>>>(out);
}